// round 10
// baseline (speedup 1.0000x reference)
#include <cuda_runtime.h>

#define BT   4096
#define Hd   512
#define G4   2048   // 4*H
#define Ed   256
#define Lc   16
#define VOC  256

// ---------------- device scratch (no allocations allowed) ----------------
__device__ float    g_table[VOC * G4];   // bias + emb @ W_ih^T  (2 MB)
__device__ unsigned g_Wt[G4 * Hd];       // W_hh as tf32 bits    (4 MB)
__device__ float    g_hA[BT * Hd];
__device__ float    g_hB[BT * Hd];
__device__ unsigned g_hAt[BT * Hd];      // tf32 copies of h (GEMM A operand)
__device__ unsigned g_hBt[BT * Hd];
__device__ float    g_c[BT * Hd];

// ---------------- helpers ----------------
__device__ __forceinline__ unsigned f2tf32(float x) {
    unsigned u; asm("cvt.rna.tf32.f32 %0, %1;" : "=r"(u) : "f"(x)); return u;
}
__device__ __forceinline__ float sigf(float x)  { return 1.f / (1.f + __expf(-x)); }
__device__ __forceinline__ float tanh_(float x) { return 2.f / (1.f + __expf(-2.f * x)) - 1.f; }

__device__ __forceinline__ unsigned s2u(const void* p) {
    unsigned r;
    asm("{.reg .u64 t; cvta.to.shared.u64 t, %1; cvt.u32.u64 %0, t;}" : "=r"(r) : "l"(p));
    return r;
}
__device__ __forceinline__ void cp16(unsigned d, const void* s) {
    asm volatile("cp.async.cg.shared.global [%0], [%1], 16;" :: "r"(d), "l"(s));
}
__device__ __forceinline__ void ldsm4(unsigned* f, unsigned addr) {
    asm volatile("ldmatrix.sync.aligned.m8n8.x4.shared.b16 {%0,%1,%2,%3}, [%4];"
                 : "=r"(f[0]), "=r"(f[1]), "=r"(f[2]), "=r"(f[3]) : "r"(addr));
}

// ---------------- kernel 1: table[v][n] = b_ih[n]+b_hh[n] + sum_e emb[v][e]*W_ih[n][e]
__global__ void k_table(const float* __restrict__ emb, const float* __restrict__ Wih,
                        const float* __restrict__ bih, const float* __restrict__ bhh) {
    __shared__ float Es[64][65];
    __shared__ float Ws[64][65];
    int tid = threadIdx.x;
    int n0 = blockIdx.x * 64;
    int v0 = blockIdx.y * 64;

    float acc[16];
    #pragma unroll
    for (int i = 0; i < 16; i++) acc[i] = 0.f;

    int lrow = tid >> 2;   // 0..63
    int lq   = tid & 3;    // 0..3

    for (int e0 = 0; e0 < Ed; e0 += 64) {
        #pragma unroll
        for (int i = 0; i < 4; i++) {
            int c4 = lq + i * 4;
            float4 ev = *(const float4*)&emb[(v0 + lrow) * Ed + e0 + c4 * 4];
            float4 wv = *(const float4*)&Wih[(n0 + lrow) * Ed + e0 + c4 * 4];
            Es[lrow][c4 * 4 + 0] = ev.x; Es[lrow][c4 * 4 + 1] = ev.y;
            Es[lrow][c4 * 4 + 2] = ev.z; Es[lrow][c4 * 4 + 3] = ev.w;
            Ws[lrow][c4 * 4 + 0] = wv.x; Ws[lrow][c4 * 4 + 1] = wv.y;
            Ws[lrow][c4 * 4 + 2] = wv.z; Ws[lrow][c4 * 4 + 3] = wv.w;
        }
        __syncthreads();
        int tn = tid & 63;
        int tv = tid >> 6;
        #pragma unroll 8
        for (int e = 0; e < 64; e++) {
            float w = Ws[tn][e];
            #pragma unroll
            for (int vv = 0; vv < 16; vv++)
                acc[vv] = fmaf(Es[tv * 16 + vv][e], w, acc[vv]);
        }
        __syncthreads();
    }
    int tn = tid & 63, tv = tid >> 6;
    float bias = bih[n0 + tn] + bhh[n0 + tn];
    #pragma unroll
    for (int vv = 0; vv < 16; vv++)
        g_table[(v0 + tv * 16 + vv) * G4 + n0 + tn] = acc[vv] + bias;
}

// ---------------- kernel 2: W_hh -> tf32 bits ----------------
__global__ void k_cvtW(const float* __restrict__ W) {
    int i = (blockIdx.x * blockDim.x + threadIdx.x) * 4;
    float4 w = *(const float4*)(W + i);
    uint4 o;
    o.x = f2tf32(w.x); o.y = f2tf32(w.y); o.z = f2tf32(w.z); o.w = f2tf32(w.w);
    *(uint4*)(g_Wt + i) = o;
}

// ---------------- kernel 3: step 0 (h=c=0 -> pure table->cell) ----------------
__global__ void k_step0(const int* __restrict__ chars) {
    int idx = blockIdx.x * 256 + threadIdx.x;   // idx = r*512 + j
    int r = idx >> 9;
    int j = idx & 511;
    int id = __ldg(&chars[r * Lc]);
    const float* tb = g_table + id * G4 + j;
    float iv = sigf(tb[0]);
    float gv = tanh_(tb[1024]);
    float ov = sigf(tb[1536]);
    float cn = iv * gv;               // f*c0 = 0
    float hn = ov * tanh_(cn);        // mask always 1 at t=0 (lens >= 1)
    g_c[idx]   = cn;
    g_hA[idx]  = hn;
    g_hAt[idx] = f2tf32(hn);
}

// ---------------- kernel 4: fused GEMM (tf32 mma + ldmatrix) + LSTM cell ----------------
// Block tile: 128 rows x 128 gate-rows. 512 threads, 16 warps in 4x4 grid,
// warp tile 32x32. K=512 in 16 chunks of 32, 3-stage cp.async ring.
// Anti-phase-lock: each warp walks the four k8 sub-chunks in rotated order
// (ks = (ksi + warp&3) & 3) so LDSM storms and MMA bursts from different warps
// interleave instead of aligning behind the block barrier.
__global__ __launch_bounds__(512, 2)
void k_step(int t, int dir, float* __restrict__ finalOut,
            const int* __restrict__ chars, const int* __restrict__ lens) {
    extern __shared__ unsigned sm[];
    const unsigned* hin_t = dir ? g_hBt : g_hAt;
    const float*    hin_f = dir ? g_hB  : g_hA;
    float*    hout_f = finalOut ? finalOut : (dir ? g_hA : g_hB);
    unsigned* hout_t = dir ? g_hAt : g_hBt;

    const int tid  = threadIdx.x;
    const int lane = tid & 31, warp = tid >> 5;
    const int wm = warp >> 2, wn = warp & 3;       // 4x4 warps -> 32x32 warp tile
    const int j0 = blockIdx.x * 32;
    const int m0 = blockIdx.y * 128;
    const int kph = warp & 3;                      // per-warp k8 rotation

    const unsigned smaddr = s2u(sm);
    const int SA = 36, ABUF = 128 * 36, BOFF = 3 * ABUF;   // u32 units, 3 stages
    const int ROWB = SA * 4;                               // 144 B per row

    float acc[2][4][4];
    #pragma unroll
    for (int a = 0; a < 2; a++)
        #pragma unroll
        for (int b = 0; b < 4; b++)
            #pragma unroll
            for (int cc = 0; cc < 4; cc++) acc[a][b][cc] = 0.f;

    // ---- staging addresses (512 threads: each stages 2 A rows + 2 B rows) ----
    const int lrow = tid >> 3;   // 0..63
    const int lq   = tid & 7;    // 16B chunk within a 32-float row
    const unsigned* asrc[2];
    const unsigned* bsrc[2];
    unsigned rdst[2];
    #pragma unroll
    for (int p = 0; p < 2; p++) {
        int r = lrow + p * 64;                      // row 0..127
        asrc[p] = hin_t + (m0 + r) * Hd + lq * 4;
        int wr  = (r >> 5) * Hd + j0 + (r & 31);    // W_hh row: gate*512 + j
        bsrc[p] = g_Wt + wr * Hd + lq * 4;
        rdst[p] = (unsigned)(r * SA + lq * 4) * 4u;
    }

    auto stage = [&](int c, int buf) {
        unsigned abase = smaddr + (unsigned)(buf * ABUF) * 4u;
        unsigned bbase = smaddr + (unsigned)(BOFF + buf * ABUF) * 4u;
        int k0 = c * 32;
        #pragma unroll
        for (int p = 0; p < 2; p++) cp16(abase + rdst[p], asrc[p] + k0);
        #pragma unroll
        for (int p = 0; p < 2; p++) cp16(bbase + rdst[p], bsrc[p] + k0);
        asm volatile("cp.async.commit_group;");
    };

    stage(0, 0);
    stage(1, 1);

    // ---- ldmatrix lane base offsets (bytes within a buffer) ----
    const unsigned aoff = (unsigned)((wm * 32 + (lane & 15)) * ROWB + (lane >> 4) * 16);
    const unsigned boff = (unsigned)((wn * 32 + ((lane >> 4) << 3) + (lane & 7)) * ROWB
                                     + ((lane >> 3) & 1) * 16);

    auto body = [&](int kt, int buf, bool last) {
        if (!last) asm volatile("cp.async.wait_group 1;");
        else       asm volatile("cp.async.wait_group 0;");
        __syncthreads();
        if (!last && kt + 2 < 16) stage(kt + 2, (buf + 2) % 3);

        const unsigned aBase = smaddr + (unsigned)(buf * ABUF) * 4u + aoff;
        const unsigned bBase = smaddr + (unsigned)((BOFF + buf * ABUF)) * 4u + boff;

        #pragma unroll
        for (int ksi = 0; ksi < 4; ++ksi) {
            const int ks = (ksi + kph) & 3;        // rotated sub-chunk order
            unsigned af[2][4], bf4[2][4];
            #pragma unroll
            for (int mi = 0; mi < 2; mi++)
                ldsm4(af[mi], aBase + (unsigned)(mi * 16 * ROWB) + (unsigned)(ks * 32));
            #pragma unroll
            for (int p = 0; p < 2; p++)
                ldsm4(bf4[p], bBase + (unsigned)(p * 16 * ROWB) + (unsigned)(ks * 32));

            #pragma unroll
            for (int mi = 0; mi < 2; mi++)
                #pragma unroll
                for (int ni = 0; ni < 4; ni++) {
                    unsigned b0 = bf4[ni >> 1][(ni & 1) * 2];
                    unsigned b1 = bf4[ni >> 1][(ni & 1) * 2 + 1];
                    asm volatile(
                        "mma.sync.aligned.m16n8k8.row.col.f32.tf32.tf32.f32 "
                        "{%0,%1,%2,%3}, {%4,%5,%6,%7}, {%8,%9}, {%0,%1,%2,%3};"
                        : "+f"(acc[mi][ni][0]), "+f"(acc[mi][ni][1]),
                          "+f"(acc[mi][ni][2]), "+f"(acc[mi][ni][3])
                        : "r"(af[mi][0]), "r"(af[mi][1]), "r"(af[mi][2]), "r"(af[mi][3]),
                          "r"(b0), "r"(b1));
                }
        }
    };

    // 15 chunks in groups of 3 (buffer ids compile-time constant), then tail.
    for (int kb = 0; kb < 15; kb += 3) {
        body(kb + 0, 0, false);
        body(kb + 1, 1, false);
        body(kb + 2, 2, false);
    }
    body(15, 0, true);

    __syncthreads();   // all fragment reads done before smem reuse

    // ---------- epilogue: exchange accums through smem, then fused LSTM cell ----------
    float* epi = (float*)sm;                    // 128 x 132 floats (reuses GEMM smem)
    #pragma unroll
    for (int mi = 0; mi < 2; mi++)
        #pragma unroll
        for (int ni = 0; ni < 4; ni++) {
            int r  = wm * 32 + mi * 16 + (lane >> 2);
            int cb = wn * 32 + ni * 8 + (lane & 3) * 2;
            epi[r * 132 + cb]           = acc[mi][ni][0];
            epi[r * 132 + cb + 1]       = acc[mi][ni][1];
            epi[(r + 8) * 132 + cb]     = acc[mi][ni][2];
            epi[(r + 8) * 132 + cb + 1] = acc[mi][ni][3];
        }
    __syncthreads();

    const int jj = tid & 31;
    const int rb = tid >> 5;     // 0..15
    #pragma unroll
    for (int p = 0; p < 8; p++) {
        int rl = rb + p * 16;
        int r  = m0 + rl;
        int id = __ldg(&chars[r * Lc + t]);
        int j  = j0 + jj;
        const float* tb = g_table + id * G4 + j;
        float iv = epi[rl * 132 + jj]       + tb[0];
        float fv = epi[rl * 132 + 32 + jj]  + tb[512];
        float gv = epi[rl * 132 + 64 + jj]  + tb[1024];
        float ov = epi[rl * 132 + 96 + jj]  + tb[1536];
        float ig = sigf(iv), fg = sigf(fv), gg = tanh_(gv), og = sigf(ov);
        int gi = r * Hd + j;
        float co = g_c[gi];
        float cn = fmaf(fg, co, ig * gg);
        float hn = og * tanh_(cn);
        bool  mk = __ldg(&lens[r]) > t;
        float hv = mk ? hn : hin_f[gi];
        float cv = mk ? cn : co;
        g_c[gi]    = cv;
        hout_f[gi] = hv;
        hout_t[gi] = f2tf32(hv);
    }
}

// ---------------- launcher ----------------
extern "C" void kernel_launch(void* const* d_in, const int* in_sizes, int n_in,
                              void* d_out, int out_size) {
    const int*   chars = (const int*)d_in[0];
    const int*   lens  = (const int*)d_in[1];
    const float* emb   = (const float*)d_in[2];
    const float* Wih   = (const float*)d_in[3];
    const float* Whh   = (const float*)d_in[4];
    const float* bih   = (const float*)d_in[5];
    const float* bhh   = (const float*)d_in[6];
    float* out = (float*)d_out;

    cudaFuncSetAttribute(k_step, cudaFuncAttributeMaxDynamicSharedMemorySize, 110592);

    k_table<<<dim3(32, 4), 256>>>(emb, Wih, bih, bhh);
    k_cvtW<<<1024, 256>>>(Whh);
    k_step0<<<8192, 256>>>(chars);
    for (int t = 1; t < 16; ++t) {
        int dir = (t - 1) & 1;                  // 0: in=A out=B, 1: in=B out=A
        float* fo = (t == 15) ? out : nullptr;
        k_step<<<dim3(16, 32), 512, 110592>>>(t, dir, fo, chars, lens);
    }
}

// round 11
// speedup vs baseline: 1.6508x; 1.6508x over previous
#include <cuda_runtime.h>

#define BT   4096
#define Hd   512
#define G4   2048   // 4*H
#define Ed   256
#define Lc   16
#define VOC  256

// ---------------- device scratch (no allocations allowed) ----------------
__device__ float    g_table[VOC * G4];   // bias + emb @ W_ih^T  (2 MB)
__device__ unsigned g_Wt[G4 * Hd];       // W_hh as tf32 bits    (4 MB)
__device__ float    g_hA[BT * Hd];       // h (PERMUTED row order)
__device__ float    g_hB[BT * Hd];
__device__ unsigned g_hAt[BT * Hd];      // tf32 copies of h (GEMM A operand)
__device__ unsigned g_hBt[BT * Hd];
__device__ float    g_c[BT * Hd];        // cell state (permuted, in-place)
__device__ int      g_perm[BT];          // permuted pos -> original row
__device__ int      g_plen[BT];          // permuted pos -> length
__device__ int      g_cnt[Lc];           // g_cnt[t] = #rows with len > t

// ---------------- helpers ----------------
__device__ __forceinline__ unsigned f2tf32(float x) {
    unsigned u; asm("cvt.rna.tf32.f32 %0, %1;" : "=r"(u) : "f"(x)); return u;
}
__device__ __forceinline__ float sigf(float x)  { return 1.f / (1.f + __expf(-x)); }
__device__ __forceinline__ float tanh_(float x) { return 2.f / (1.f + __expf(-2.f * x)) - 1.f; }

__device__ __forceinline__ unsigned s2u(const void* p) {
    unsigned r;
    asm("{.reg .u64 t; cvta.to.shared.u64 t, %1; cvt.u32.u64 %0, t;}" : "=r"(r) : "l"(p));
    return r;
}
__device__ __forceinline__ void cp16(unsigned d, const void* s) {
    asm volatile("cp.async.cg.shared.global [%0], [%1], 16;" :: "r"(d), "l"(s));
}
__device__ __forceinline__ void ldsm4(unsigned* f, unsigned addr) {
    asm volatile("ldmatrix.sync.aligned.m8n8.x4.shared.b16 {%0,%1,%2,%3}, [%4];"
                 : "=r"(f[0]), "=r"(f[1]), "=r"(f[2]), "=r"(f[3]) : "r"(addr));
}

// ---------------- kernel 0: counting sort by descending length ----------------
__global__ void k_sort(const int* __restrict__ lens) {
    __shared__ int hist[17];
    __shared__ int base[17];
    int tid = threadIdx.x;
    if (tid < 17) hist[tid] = 0;
    __syncthreads();
    for (int r = tid; r < BT; r += 256) atomicAdd(&hist[lens[r]], 1);
    __syncthreads();
    if (tid == 0) {
        int s = 0;
        for (int L = 16; L >= 1; --L) { base[L] = s; s += hist[L]; }
        for (int t2 = 1; t2 < 16; t2++) g_cnt[t2] = base[t2];  // #{len > t}
    }
    __syncthreads();
    for (int r = tid; r < BT; r += 256) {
        int L = lens[r];
        int pos = atomicAdd(&base[L], 1);
        g_perm[pos] = r;
        g_plen[pos] = L;
    }
}

// ---------------- kernel 1: table[v][n] = b_ih[n]+b_hh[n] + sum_e emb[v][e]*W_ih[n][e]
__global__ void k_table(const float* __restrict__ emb, const float* __restrict__ Wih,
                        const float* __restrict__ bih, const float* __restrict__ bhh) {
    __shared__ float Es[64][65];
    __shared__ float Ws[64][65];
    int tid = threadIdx.x;
    int n0 = blockIdx.x * 64;
    int v0 = blockIdx.y * 64;

    float acc[16];
    #pragma unroll
    for (int i = 0; i < 16; i++) acc[i] = 0.f;

    int lrow = tid >> 2;   // 0..63
    int lq   = tid & 3;    // 0..3

    for (int e0 = 0; e0 < Ed; e0 += 64) {
        #pragma unroll
        for (int i = 0; i < 4; i++) {
            int c4 = lq + i * 4;
            float4 ev = *(const float4*)&emb[(v0 + lrow) * Ed + e0 + c4 * 4];
            float4 wv = *(const float4*)&Wih[(n0 + lrow) * Ed + e0 + c4 * 4];
            Es[lrow][c4 * 4 + 0] = ev.x; Es[lrow][c4 * 4 + 1] = ev.y;
            Es[lrow][c4 * 4 + 2] = ev.z; Es[lrow][c4 * 4 + 3] = ev.w;
            Ws[lrow][c4 * 4 + 0] = wv.x; Ws[lrow][c4 * 4 + 1] = wv.y;
            Ws[lrow][c4 * 4 + 2] = wv.z; Ws[lrow][c4 * 4 + 3] = wv.w;
        }
        __syncthreads();
        int tn = tid & 63;
        int tv = tid >> 6;
        #pragma unroll 8
        for (int e = 0; e < 64; e++) {
            float w = Ws[tn][e];
            #pragma unroll
            for (int vv = 0; vv < 16; vv++)
                acc[vv] = fmaf(Es[tv * 16 + vv][e], w, acc[vv]);
        }
        __syncthreads();
    }
    int tn = tid & 63, tv = tid >> 6;
    float bias = bih[n0 + tn] + bhh[n0 + tn];
    #pragma unroll
    for (int vv = 0; vv < 16; vv++)
        g_table[(v0 + tv * 16 + vv) * G4 + n0 + tn] = acc[vv] + bias;
}

// ---------------- kernel 2: W_hh -> tf32 bits ----------------
__global__ void k_cvtW(const float* __restrict__ W) {
    int i = (blockIdx.x * blockDim.x + threadIdx.x) * 4;
    float4 w = *(const float4*)(W + i);
    uint4 o;
    o.x = f2tf32(w.x); o.y = f2tf32(w.y); o.z = f2tf32(w.z); o.w = f2tf32(w.w);
    *(uint4*)(g_Wt + i) = o;
}

// ---------------- kernel 3: step 0 (h=c=0), permuted storage ----------------
__global__ void k_step0(const int* __restrict__ chars) {
    int idx = blockIdx.x * 256 + threadIdx.x;   // idx = permpos*512 + j
    int r = idx >> 9;
    int j = idx & 511;
    int orig = __ldg(&g_perm[r]);
    int id = __ldg(&chars[orig * Lc]);
    const float* tb = g_table + id * G4 + j;
    float iv = sigf(tb[0]);
    float gv = tanh_(tb[1024]);
    float ov = sigf(tb[1536]);
    float cn = iv * gv;               // f*c0 = 0
    float hn = ov * tanh_(cn);        // all rows active at t=0 (lens >= 1)
    g_c[idx]   = cn;
    g_hA[idx]  = hn;
    g_hAt[idx] = f2tf32(hn);
}

// ---------------- kernel 4: fused GEMM (tf32 mma + ldmatrix) + LSTM cell ----------------
// Block tile: 128 rows x 128 gate-rows. 512 threads, 16 warps in 4x4 grid,
// warp tile 32x32. K=512 in 16 chunks of 32, 3-stage cp.async ring.
// Rows are length-sorted: CTAs beyond g_cnt[t] exit; frozen rows skip writes.
__global__ __launch_bounds__(512, 2)
void k_step(int t, int dir, const int* __restrict__ chars) {
    extern __shared__ unsigned sm[];
    const int m0 = blockIdx.y * 128;
    if (m0 >= g_cnt[t]) return;                    // uniform early exit

    const unsigned* hin_t = dir ? g_hBt : g_hAt;
    float*    hout_f = dir ? g_hA  : g_hB;
    unsigned* hout_t = dir ? g_hAt : g_hBt;

    const int tid  = threadIdx.x;
    const int lane = tid & 31, warp = tid >> 5;
    const int wm = warp >> 2, wn = warp & 3;       // 4x4 warps -> 32x32 warp tile
    const int j0 = blockIdx.x * 32;

    const unsigned smaddr = s2u(sm);
    const int SA = 36, ABUF = 128 * 36, BOFF = 3 * ABUF;   // u32 units, 3 stages
    const int ROWB = SA * 4;                               // 144 B per row

    float acc[2][4][4];
    #pragma unroll
    for (int a = 0; a < 2; a++)
        #pragma unroll
        for (int b = 0; b < 4; b++)
            #pragma unroll
            for (int cc = 0; cc < 4; cc++) acc[a][b][cc] = 0.f;

    // ---- staging addresses (512 threads: each stages 2 A rows + 2 B rows) ----
    const int lrow = tid >> 3;   // 0..63
    const int lq   = tid & 7;    // 16B chunk within a 32-float row
    const unsigned* asrc[2];
    const unsigned* bsrc[2];
    unsigned rdst[2];
    #pragma unroll
    for (int p = 0; p < 2; p++) {
        int r = lrow + p * 64;                      // row 0..127
        asrc[p] = hin_t + (m0 + r) * Hd + lq * 4;
        int wr  = (r >> 5) * Hd + j0 + (r & 31);    // W_hh row: gate*512 + j
        bsrc[p] = g_Wt + wr * Hd + lq * 4;
        rdst[p] = (unsigned)(r * SA + lq * 4) * 4u;
    }

    auto stage = [&](int c, int buf) {
        unsigned abase = smaddr + (unsigned)(buf * ABUF) * 4u;
        unsigned bbase = smaddr + (unsigned)(BOFF + buf * ABUF) * 4u;
        int k0 = c * 32;
        #pragma unroll
        for (int p = 0; p < 2; p++) cp16(abase + rdst[p], asrc[p] + k0);
        #pragma unroll
        for (int p = 0; p < 2; p++) cp16(bbase + rdst[p], bsrc[p] + k0);
        asm volatile("cp.async.commit_group;");
    };

    stage(0, 0);
    stage(1, 1);

    // ---- ldmatrix lane base offsets (bytes within a buffer) ----
    const unsigned aoff = (unsigned)((wm * 32 + (lane & 15)) * ROWB + (lane >> 4) * 16);
    const unsigned boff = (unsigned)((wn * 32 + ((lane >> 4) << 3) + (lane & 7)) * ROWB
                                     + ((lane >> 3) & 1) * 16);

    auto body = [&](int kt, int buf, bool last) {
        if (!last) asm volatile("cp.async.wait_group 1;");
        else       asm volatile("cp.async.wait_group 0;");
        __syncthreads();
        if (!last && kt + 2 < 16) stage(kt + 2, (buf + 2) % 3);

        const unsigned aBase = smaddr + (unsigned)(buf * ABUF) * 4u + aoff;
        const unsigned bBase = smaddr + (unsigned)((BOFF + buf * ABUF)) * 4u + boff;

        #pragma unroll
        for (int ks = 0; ks < 4; ++ks) {
            unsigned af[2][4], bf4[2][4];
            #pragma unroll
            for (int mi = 0; mi < 2; mi++)
                ldsm4(af[mi], aBase + (unsigned)(mi * 16 * ROWB + ks * 32));
            #pragma unroll
            for (int p = 0; p < 2; p++)
                ldsm4(bf4[p], bBase + (unsigned)(p * 16 * ROWB + ks * 32));

            #pragma unroll
            for (int mi = 0; mi < 2; mi++)
                #pragma unroll
                for (int ni = 0; ni < 4; ni++) {
                    unsigned b0 = bf4[ni >> 1][(ni & 1) * 2];
                    unsigned b1 = bf4[ni >> 1][(ni & 1) * 2 + 1];
                    asm volatile(
                        "mma.sync.aligned.m16n8k8.row.col.f32.tf32.tf32.f32 "
                        "{%0,%1,%2,%3}, {%4,%5,%6,%7}, {%8,%9}, {%0,%1,%2,%3};"
                        : "+f"(acc[mi][ni][0]), "+f"(acc[mi][ni][1]),
                          "+f"(acc[mi][ni][2]), "+f"(acc[mi][ni][3])
                        : "r"(af[mi][0]), "r"(af[mi][1]), "r"(af[mi][2]), "r"(af[mi][3]),
                          "r"(b0), "r"(b1));
                }
        }
    };

    // 15 chunks in groups of 3 (buffer ids compile-time constant), then tail.
    for (int kb = 0; kb < 15; kb += 3) {
        body(kb + 0, 0, false);
        body(kb + 1, 1, false);
        body(kb + 2, 2, false);
    }
    body(15, 0, true);

    __syncthreads();   // all fragment reads done before smem reuse

    // ---------- epilogue: exchange accums through smem, then fused LSTM cell ----------
    float* epi = (float*)sm;                    // 128 x 132 floats (reuses GEMM smem)
    #pragma unroll
    for (int mi = 0; mi < 2; mi++)
        #pragma unroll
        for (int ni = 0; ni < 4; ni++) {
            int r  = wm * 32 + mi * 16 + (lane >> 2);
            int cb = wn * 32 + ni * 8 + (lane & 3) * 2;
            epi[r * 132 + cb]           = acc[mi][ni][0];
            epi[r * 132 + cb + 1]       = acc[mi][ni][1];
            epi[(r + 8) * 132 + cb]     = acc[mi][ni][2];
            epi[(r + 8) * 132 + cb + 1] = acc[mi][ni][3];
        }
    __syncthreads();

    const int jj = tid & 31;
    const int rb = tid >> 5;     // 0..15
    #pragma unroll
    for (int p = 0; p < 8; p++) {
        int rl = rb + p * 16;
        int r  = m0 + rl;                           // permuted row index
        bool mk = __ldg(&g_plen[r]) > t;
        if (!mk) continue;                          // frozen: leave h, c untouched
        int orig = __ldg(&g_perm[r]);
        int id = __ldg(&chars[orig * Lc + t]);
        int j  = j0 + jj;
        const float* tb = g_table + id * G4 + j;
        float iv = epi[rl * 132 + jj]       + tb[0];
        float fv = epi[rl * 132 + 32 + jj]  + tb[512];
        float gv = epi[rl * 132 + 64 + jj]  + tb[1024];
        float ov = epi[rl * 132 + 96 + jj]  + tb[1536];
        float ig = sigf(iv), fg = sigf(fv), gg = tanh_(gv), og = sigf(ov);
        int gi = r * Hd + j;
        float co = g_c[gi];
        float cn = fmaf(fg, co, ig * gg);
        float hn = og * tanh_(cn);
        g_c[gi]    = cn;
        hout_f[gi] = hn;
        hout_t[gi] = f2tf32(hn);
    }
}

// ---------------- kernel 5: un-permute final h into out ----------------
// Row of length L was last written at step L-1: L odd -> g_hA, L even -> g_hB.
__global__ void k_scatter(float* __restrict__ out) {
    int idx = (blockIdx.x * 256 + threadIdx.x) * 4;
    int i = idx >> 9;            // permuted pos
    int j = idx & 511;
    int orig = __ldg(&g_perm[i]);
    int L    = __ldg(&g_plen[i]);
    const float* src = (L & 1) ? g_hA : g_hB;
    float4 v = *(const float4*)(src + i * Hd + j);
    *(float4*)(out + orig * Hd + j) = v;
}

// ---------------- launcher ----------------
extern "C" void kernel_launch(void* const* d_in, const int* in_sizes, int n_in,
                              void* d_out, int out_size) {
    const int*   chars = (const int*)d_in[0];
    const int*   lens  = (const int*)d_in[1];
    const float* emb   = (const float*)d_in[2];
    const float* Wih   = (const float*)d_in[3];
    const float* Whh   = (const float*)d_in[4];
    const float* bih   = (const float*)d_in[5];
    const float* bhh   = (const float*)d_in[6];
    float* out = (float*)d_out;

    cudaFuncSetAttribute(k_step, cudaFuncAttributeMaxDynamicSharedMemorySize, 110592);

    k_sort<<<1, 256>>>(lens);
    k_table<<<dim3(32, 4), 256>>>(emb, Wih, bih, bhh);
    k_cvtW<<<1024, 256>>>(Whh);
    k_step0<<<8192, 256>>>(chars);
    for (int t = 1; t < 16; ++t) {
        int dir = (t - 1) & 1;                  // 0: in=A out=B, 1: in=B out=A
        k_step<<<dim3(16, 32), 512, 110592>>>(t, dir, chars);
    }
    k_scatter<<<2048, 256>>>(out);
}